// round 7
// baseline (speedup 1.0000x reference)
#include <cuda_runtime.h>
#include <math.h>

#define BATCH 4
#define NPTS  4096
#define KNBR  16
#define DP    64
#define DM    128
#define PPB   2                 // points per block in kernel C
#define NS    (PPB*KNBR)        // 32 (point,k) slots
#define KROW  36                // padded transposed-row length (floats); 4t%32 start banks -> conflict-free STS.128

#define KNN_BLOCKS  (BATCH*NPTS/4)    // 4096 (1 warp/query, 4 warps/block)
#define QKV_BLOCKS  (BATCH*NPTS/16)   // 1024 (16 points/block)

typedef unsigned long long ull;

// ---- packed f32x2 helpers (sm_103a FFMA2 path) ----
__device__ __forceinline__ ull pack2(float lo, float hi) {
    ull r; asm("mov.b64 %0, {%1, %2};" : "=l"(r) : "f"(lo), "f"(hi)); return r;
}
__device__ __forceinline__ void unpack2(ull v, float& lo, float& hi) {
    asm("mov.b64 {%0, %1}, %2;" : "=f"(lo), "=f"(hi) : "l"(v));
}
__device__ __forceinline__ ull ffma2(ull a, ull b, ull c) {
    ull d; asm("fma.rn.f32x2 %0, %1, %2, %3;" : "=l"(d) : "l"(a), "l"(b), "l"(c)); return d;
}

// ---- scratch (no allocation allowed; __device__ globals) ----
__device__ float g_q [BATCH*NPTS*DM];
__device__ float g_kf[BATCH*NPTS*DM];
__device__ float g_vf[BATCH*NPTS*DM];
__device__ int   g_knn[BATCH*NPTS*KNBR];

// ============================================================
// Fused kernel AB: blocks [0, QKV_BLOCKS) do qkv projections (long
// blocks first for wave balance), blocks [QKV_BLOCKS, +KNN_BLOCKS)
// do exact KNN. The two halves are independent; fusing overlaps them.
// ============================================================

struct QkvSmem {                 // 12.3 KB
    float fsh[16][DP];
    float xsh[16][DM];
};
struct KnnSmem {                 // 17.4 KB
    float md[4][32][17];
    int   mi[4][32][17];
};
union __align__(16) ABSmem { QkvSmem q; KnnSmem k; };

__device__ __forceinline__ void qkv_body(
    ABSmem& sm, int blk,
    const float* __restrict__ feat,
    const float* __restrict__ fc1w, const float* __restrict__ fc1b,
    const float* __restrict__ wq, const float* __restrict__ wk,
    const float* __restrict__ wv)
{
    constexpr int P = 16;
    auto& fsh = sm.q.fsh;
    auto& xsh = sm.q.xsh;
    int t = threadIdx.x;
    int base = blk * P;

    for (int i = t; i < P*DP; i += 128)
        fsh[i >> 6][i & 63] = feat[base*DP + i];
    __syncthreads();

    float acc[P];
    {
        float bb = fc1b[t];
        #pragma unroll
        for (int p = 0; p < P; ++p) acc[p] = bb;
        for (int c = 0; c < DP; ++c) {
            float w = fc1w[c*DM + t];
            #pragma unroll
            for (int p = 0; p < P; ++p) acc[p] = fmaf(fsh[p][c], w, acc[p]);
        }
    }
    #pragma unroll
    for (int p = 0; p < P; ++p) xsh[p][t] = acc[p];
    __syncthreads();

    const float* Ws[3] = { wq, wk, wv };
    float* Os[3] = { g_q, g_kf, g_vf };
    for (int m = 0; m < 3; ++m) {
        const float* W = Ws[m];
        #pragma unroll
        for (int p = 0; p < P; ++p) acc[p] = 0.f;
        for (int c = 0; c < DM; c += 4) {
            float w0 = W[(c+0)*DM + t];
            float w1 = W[(c+1)*DM + t];
            float w2 = W[(c+2)*DM + t];
            float w3 = W[(c+3)*DM + t];
            #pragma unroll
            for (int p = 0; p < P; ++p) {
                float4 x4 = *reinterpret_cast<const float4*>(&xsh[p][c]);
                acc[p] = fmaf(x4.x, w0, fmaf(x4.y, w1, fmaf(x4.z, w2, fmaf(x4.w, w3, acc[p]))));
            }
        }
        float* O = Os[m];
        #pragma unroll
        for (int p = 0; p < P; ++p) O[(base + p)*DM + t] = acc[p];
    }
}

__device__ __forceinline__ void knn_body(
    ABSmem& sm, int blk, const float* __restrict__ xyz)
{
    auto& md = sm.k.md;
    auto& mi = sm.k.mi;

    int warp = threadIdx.x >> 5;
    int lane = threadIdx.x & 31;
    int q = blk * 4 + warp;                  // global query id in [0, B*N)
    int b = q >> 12;
    int n = q & (NPTS - 1);
    const float* xb = xyz + (size_t)b * NPTS * 3;

    float qx = xb[n*3+0], qy = xb[n*3+1], qz = xb[n*3+2];
    float qsq = fmaf(qz, qz, fmaf(qy, qy, qx*qx));

    float bd[KNBR]; int bi[KNBR];
    #pragma unroll
    for (int i = 0; i < KNBR; ++i) { bd[i] = INFINITY; bi[i] = 0x7fffffff; }

    for (int m = lane; m < NPTS; m += 32) {
        float cx = xb[m*3+0], cy = xb[m*3+1], cz = xb[m*3+2];
        float csq = fmaf(cz, cz, fmaf(cy, cy, cx*cx));
        float dot = fmaf(qz, cz, fmaf(qy, cy, qx*cx));
        float d = (qsq + csq) - 2.0f * dot;   // same formula as reference

        bool ins = (d < bd[KNBR-1]) || (d == bd[KNBR-1] && m < bi[KNBR-1]);
        if (ins) {
            bd[KNBR-1] = d; bi[KNBR-1] = m;
            #pragma unroll
            for (int j = KNBR-1; j > 0; --j) {
                bool sw = (bd[j] < bd[j-1]) || (bd[j] == bd[j-1] && bi[j] < bi[j-1]);
                if (sw) {
                    float td = bd[j]; bd[j] = bd[j-1]; bd[j-1] = td;
                    int   ti = bi[j]; bi[j] = bi[j-1]; bi[j-1] = ti;
                }
            }
        }
    }

    #pragma unroll
    for (int i = 0; i < KNBR; ++i) { md[warp][lane][i] = bd[i]; mi[warp][lane][i] = bi[i]; }
    md[warp][lane][KNBR] = INFINITY;
    mi[warp][lane][KNBR] = 0x7fffffff;
    __syncwarp();

    int ptr = 0;
    for (int r = 0; r < KNBR; ++r) {
        float d = md[warp][lane][ptr];
        int   i = mi[warp][lane][ptr];
        float rd = d; int ri = i;
        #pragma unroll
        for (int off = 16; off; off >>= 1) {
            float od = __shfl_down_sync(0xffffffffu, rd, off);
            int   oi = __shfl_down_sync(0xffffffffu, ri, off);
            if (od < rd || (od == rd && oi < ri)) { rd = od; ri = oi; }
        }
        rd = __shfl_sync(0xffffffffu, rd, 0);
        ri = __shfl_sync(0xffffffffu, ri, 0);
        if (i == ri) ptr++;                  // indices globally unique
        if (lane == 0) g_knn[q*KNBR + r] = ri;
    }
}

__global__ __launch_bounds__(128) void ab_kernel(
    const float* __restrict__ xyz, const float* __restrict__ feat,
    const float* __restrict__ fc1w, const float* __restrict__ fc1b,
    const float* __restrict__ wq, const float* __restrict__ wk,
    const float* __restrict__ wv)
{
    __shared__ ABSmem sm;
    if (blockIdx.x < QKV_BLOCKS)
        qkv_body(sm, blockIdx.x, feat, fc1w, fc1b, wq, wk, wv);
    else
        knn_body(sm, blockIdx.x - QKV_BLOCKS, xyz);
}

// ============================================================
// Kernel C: fused MLP chain, FFMA2-packed over 2 points x 16 k.
//   Transposed activation buffers buf[channel][slot], slot = p*16+k,
//   row padded to KROW=36 floats. Thread t owns channel t.
//   16 f32x2 accumulators = 32 slots. 2 points share weight streams.
// ============================================================
__global__ __launch_bounds__(128, 3) void point_kernel(
    const float* __restrict__ xyz, const float* __restrict__ feat,
    const float* __restrict__ fd1w, const float* __restrict__ fd1b,
    const float* __restrict__ fd2w, const float* __restrict__ fd2b,
    const float* __restrict__ fg1w, const float* __restrict__ fg1b,
    const float* __restrict__ fg2w, const float* __restrict__ fg2b,
    const float* __restrict__ fc2w, const float* __restrict__ fc2b,
    float* __restrict__ out_res, float* __restrict__ out_diff)
{
    __shared__ float bufH[DM][KROW];   // h1 -> h2 -> cv
    __shared__ float bufT[DM][KROW];   // tt -> diff
    __shared__ float psh[NS][DP];      // upper-half partials of fc2
    __shared__ float relsh[NS][4];
    __shared__ int   idxsh[NS];

    int t = threadIdx.x;
    int pid0 = blockIdx.x * PPB;       // first point id (b*N+n); both points same batch
    int b = pid0 >> 12;

    if (t < NS) {
        int p = t >> 4, k = t & 15;
        int pid = pid0 + p;
        int idx = g_knn[pid*KNBR + k];
        idxsh[t] = idx;
        int gpt = (b << 12) + idx;
        relsh[t][0] = xyz[pid*3+0] - xyz[gpt*3+0];
        relsh[t][1] = xyz[pid*3+1] - xyz[gpt*3+1];
        relsh[t][2] = xyz[pid*3+2] - xyz[gpt*3+2];
    }
    __syncthreads();

    // ---- stage 1: h1[t][s] = relu(rel_s @ fd1[:,t] + b) -> bufH (transposed)
    {
        float w0 = fd1w[t], w1 = fd1w[DM + t], w2 = fd1w[2*DM + t], bb = fd1b[t];
        #pragma unroll
        for (int j = 0; j < NS/4; ++j) {
            float4 v;
            v.x = fmaxf(fmaf(relsh[4*j+0][0], w0, fmaf(relsh[4*j+0][1], w1, fmaf(relsh[4*j+0][2], w2, bb))), 0.f);
            v.y = fmaxf(fmaf(relsh[4*j+1][0], w0, fmaf(relsh[4*j+1][1], w1, fmaf(relsh[4*j+1][2], w2, bb))), 0.f);
            v.z = fmaxf(fmaf(relsh[4*j+2][0], w0, fmaf(relsh[4*j+2][1], w1, fmaf(relsh[4*j+2][2], w2, bb))), 0.f);
            v.w = fmaxf(fmaf(relsh[4*j+3][0], w0, fmaf(relsh[4*j+3][1], w1, fmaf(relsh[4*j+3][2], w2, bb))), 0.f);
            *reinterpret_cast<float4*>(&bufH[t][4*j]) = v;
        }
    }
    __syncthreads();

    ull pe[NS/2];   // pos_enc for channel t, packed slot-pairs; lives to stage 6

    // ---- stage 2: pe = h1 @ fd2 + b
    {
        float bb = fd2b[t];
        ull b2 = pack2(bb, bb);
        #pragma unroll
        for (int j = 0; j < NS/2; ++j) pe[j] = b2;
        const float* W = fd2w + t;
        #pragma unroll 2
        for (int c = 0; c < DM; ++c) {
            float w = W[c*DM];
            ull w2 = pack2(w, w);
            const ulonglong2* row = reinterpret_cast<const ulonglong2*>(&bufH[c][0]);
            #pragma unroll
            for (int j = 0; j < NS/4; ++j) {
                ulonglong2 h = row[j];
                pe[2*j+0] = ffma2(h.x, w2, pe[2*j+0]);
                pe[2*j+1] = ffma2(h.y, w2, pe[2*j+1]);
            }
        }
    }

    // ---- stage 3: tt[t][s] = q_p[t] - kf_s[t] + pe[t][s] -> bufT (transposed)
    {
        float qv0 = g_q[pid0*DM + t];
        float qv1 = g_q[(pid0+1)*DM + t];
        float kf[NS];
        #pragma unroll
        for (int s = 0; s < NS; ++s)
            kf[s] = g_kf[((b << 12) + idxsh[s])*DM + t];
        #pragma unroll
        for (int j = 0; j < NS/4; ++j) {
            float qv = (j < 4) ? qv0 : qv1;     // slots 0..15 -> p0, 16..31 -> p1
            float p0, p1, p2, p3;
            unpack2(pe[2*j+0], p0, p1);
            unpack2(pe[2*j+1], p2, p3);
            float4 v;
            v.x = qv - kf[4*j+0] + p0;
            v.y = qv - kf[4*j+1] + p1;
            v.z = qv - kf[4*j+2] + p2;
            v.w = qv - kf[4*j+3] + p3;
            *reinterpret_cast<float4*>(&bufT[t][4*j]) = v;
        }
    }
    __syncthreads();   // orders: stage-2 bufH reads before stage-4 bufH writes; tt visible

    // ---- stage 4: h2[t][s] = relu(tt @ fg1 + b) -> bufH (transposed)
    {
        ull acc[NS/2];
        float bb = fg1b[t];
        ull b2 = pack2(bb, bb);
        #pragma unroll
        for (int j = 0; j < NS/2; ++j) acc[j] = b2;
        const float* W = fg1w + t;
        #pragma unroll 2
        for (int c = 0; c < DM; ++c) {
            float w = W[c*DM];
            ull w2 = pack2(w, w);
            const ulonglong2* row = reinterpret_cast<const ulonglong2*>(&bufT[c][0]);
            #pragma unroll
            for (int j = 0; j < NS/4; ++j) {
                ulonglong2 h = row[j];
                acc[2*j+0] = ffma2(h.x, w2, acc[2*j+0]);
                acc[2*j+1] = ffma2(h.y, w2, acc[2*j+1]);
            }
        }
        #pragma unroll
        for (int j = 0; j < NS/4; ++j) {
            float p0, p1, p2, p3;
            unpack2(acc[2*j+0], p0, p1);
            unpack2(acc[2*j+1], p2, p3);
            float4 v;
            v.x = fmaxf(p0, 0.f); v.y = fmaxf(p1, 0.f);
            v.z = fmaxf(p2, 0.f); v.w = fmaxf(p3, 0.f);
            *reinterpret_cast<float4*>(&bufH[t][4*j]) = v;
        }
    }
    __syncthreads();   // h2 visible; stage-4 bufT reads done before stage-5 bufT writes

    // ---- stage 5: diff = h2 @ fg2 + b -> global out_diff + bufT (transposed)
    {
        ull acc[NS/2];
        float bb = fg2b[t];
        ull b2 = pack2(bb, bb);
        #pragma unroll
        for (int j = 0; j < NS/2; ++j) acc[j] = b2;
        const float* W = fg2w + t;
        #pragma unroll 2
        for (int c = 0; c < DM; ++c) {
            float w = W[c*DM];
            ull w2 = pack2(w, w);
            const ulonglong2* row = reinterpret_cast<const ulonglong2*>(&bufH[c][0]);
            #pragma unroll
            for (int j = 0; j < NS/4; ++j) {
                ulonglong2 h = row[j];
                acc[2*j+0] = ffma2(h.x, w2, acc[2*j+0]);
                acc[2*j+1] = ffma2(h.y, w2, acc[2*j+1]);
            }
        }
        #pragma unroll
        for (int j = 0; j < NS/4; ++j) {
            int p = j >> 2;                    // point for slots 4j..4j+3
            float* OD = out_diff + ((size_t)(pid0 + p)*KNBR + ((4*j) & 15))*DM + t;
            float p0, p1, p2, p3;
            unpack2(acc[2*j+0], p0, p1);
            unpack2(acc[2*j+1], p2, p3);
            OD[0*DM] = p0;
            OD[1*DM] = p1;
            OD[2*DM] = p2;
            OD[3*DM] = p3;
            float4 v; v.x = p0; v.y = p1; v.z = p2; v.w = p3;
            *reinterpret_cast<float4*>(&bufT[t][4*j]) = v;
        }
    }
    __syncthreads();   // stage-5 bufH reads done before stage-6 bufH writes; diff visible

    // ---- stage 6: cv[t][s] = vf_s[t] + pe[t][s] -> bufH (transposed)
    {
        float vf[NS];
        #pragma unroll
        for (int s = 0; s < NS; ++s)
            vf[s] = g_vf[((b << 12) + idxsh[s])*DM + t];
        #pragma unroll
        for (int j = 0; j < NS/4; ++j) {
            float p0, p1, p2, p3;
            unpack2(pe[2*j+0], p0, p1);
            unpack2(pe[2*j+1], p2, p3);
            float4 v;
            v.x = vf[4*j+0] + p0;
            v.y = vf[4*j+1] + p1;
            v.z = vf[4*j+2] + p2;
            v.w = vf[4*j+3] + p3;
            *reinterpret_cast<float4*>(&bufH[t][4*j]) = v;
        }
    }
    __syncthreads();

    // ---- stage 7: out = [diff, cv] @ fc2 + b ; res = max_k out + feat
    {
        int d = t & 63, half = t >> 6;
        const float* W = fc2w + half*DM*DP + d;
        const float (*src)[KROW] = half ? bufH : bufT;   // half1: cv, half0: diff
        ull acc[NS/2];
        #pragma unroll
        for (int j = 0; j < NS/2; ++j) acc[j] = 0;
        #pragma unroll 2
        for (int c = 0; c < DM; ++c) {
            float w = W[c*DP];
            ull w2 = pack2(w, w);
            const ulonglong2* row = reinterpret_cast<const ulonglong2*>(&src[c][0]);
            #pragma unroll
            for (int j = 0; j < NS/4; ++j) {
                ulonglong2 h = row[j];
                acc[2*j+0] = ffma2(h.x, w2, acc[2*j+0]);
                acc[2*j+1] = ffma2(h.y, w2, acc[2*j+1]);
            }
        }
        float a7[NS];
        #pragma unroll
        for (int j = 0; j < NS/2; ++j) unpack2(acc[j], a7[2*j], a7[2*j+1]);
        if (half) {
            #pragma unroll
            for (int s = 0; s < NS; ++s) psh[s][d] = a7[s];
        }
        __syncthreads();
        if (!half) {
            float bb = fc2b[d];
            #pragma unroll
            for (int p = 0; p < PPB; ++p) {
                float m = -INFINITY;
                #pragma unroll
                for (int k = 0; k < KNBR; ++k) {
                    int s = p*KNBR + k;
                    m = fmaxf(m, a7[s] + psh[s][d] + bb);
                }
                out_res[(pid0 + p)*DP + d] = m + feat[(pid0 + p)*DP + d];
            }
        }
    }
}

// ============================================================
extern "C" void kernel_launch(void* const* d_in, const int* in_sizes, int n_in,
                              void* d_out, int out_size)
{
    const float* xyz  = (const float*)d_in[0];
    const float* feat = (const float*)d_in[1];
    const float* fc1w = (const float*)d_in[2];
    const float* fc1b = (const float*)d_in[3];
    const float* fc2w = (const float*)d_in[4];
    const float* fc2b = (const float*)d_in[5];
    const float* fd1w = (const float*)d_in[6];
    const float* fd1b = (const float*)d_in[7];
    const float* fd2w = (const float*)d_in[8];
    const float* fd2b = (const float*)d_in[9];
    const float* fg1w = (const float*)d_in[10];
    const float* fg1b = (const float*)d_in[11];
    const float* fg2w = (const float*)d_in[12];
    const float* fg2b = (const float*)d_in[13];
    const float* wq   = (const float*)d_in[14];
    const float* wk   = (const float*)d_in[15];
    const float* wv   = (const float*)d_in[16];

    float* out_res  = (float*)d_out;                       // (B,N,DP)
    float* out_diff = out_res + (size_t)BATCH*NPTS*DP;     // (B,N,K,DM)

    ab_kernel   <<<QKV_BLOCKS + KNN_BLOCKS, 128>>>(xyz, feat, fc1w, fc1b, wq, wk, wv);
    point_kernel<<<BATCH*NPTS/PPB,          128>>>(xyz, feat,
                                                   fd1w, fd1b, fd2w, fd2b,
                                                   fg1w, fg1b, fg2w, fg2b,
                                                   fc2w, fc2b, out_res, out_diff);
}

// round 12
// speedup vs baseline: 1.0069x; 1.0069x over previous
#include <cuda_runtime.h>
#include <math.h>

#define BATCH 4
#define NPTS  4096
#define KNBR  16
#define DP    64
#define DM    128
#define PPB   2                 // points per block in kernel C
#define NS    (PPB*KNBR)        // 32 (point,k) slots
#define KROW  36                // padded transposed-row length (floats)

#define KNNB  (BATCH*NPTS/128)  // 128 knn blocks (1 query per lane, 128 queries/block)
#define QKVB  (BATCH*NPTS/16)   // 1024 qkv blocks (16 points/block)

typedef unsigned long long ull;

// ---- packed f32x2 helpers (sm_103a FFMA2 path) ----
__device__ __forceinline__ ull pack2(float lo, float hi) {
    ull r; asm("mov.b64 %0, {%1, %2};" : "=l"(r) : "f"(lo), "f"(hi)); return r;
}
__device__ __forceinline__ void unpack2(ull v, float& lo, float& hi) {
    asm("mov.b64 {%0, %1}, %2;" : "=f"(lo), "=f"(hi) : "l"(v));
}
__device__ __forceinline__ ull ffma2(ull a, ull b, ull c) {
    ull d; asm("fma.rn.f32x2 %0, %1, %2, %3;" : "=l"(d) : "l"(a), "l"(b), "l"(c)); return d;
}

// ---- scratch (no allocation allowed; __device__ globals) ----
__device__ float g_q [BATCH*NPTS*DM];
__device__ float g_kf[BATCH*NPTS*DM];
__device__ float g_vf[BATCH*NPTS*DM];
__device__ int   g_knn[BATCH*NPTS*KNBR];

// ============================================================
// Fused kernel AB: blocks [0, KNNB) = KNN (long, launched first),
//                  blocks [KNNB, +QKVB) = qkv projections.
// ============================================================

struct QkvSmem {                 // 12.3 KB
    float fsh[16][DP];
    float xsh[16][DM];
};
union __align__(16) ABSmem {
    QkvSmem q;
    float xyzsh[NPTS*3];         // 49152 B == 48 KB static limit
};

__device__ __forceinline__ void qkv_body(
    QkvSmem& sm, int blk,
    const float* __restrict__ feat,
    const float* __restrict__ fc1w, const float* __restrict__ fc1b,
    const float* __restrict__ wq, const float* __restrict__ wk,
    const float* __restrict__ wv)
{
    constexpr int P = 16;
    auto& fsh = sm.fsh;
    auto& xsh = sm.xsh;
    int t = threadIdx.x;
    int base = blk * P;

    for (int i = t; i < P*DP; i += 128)
        fsh[i >> 6][i & 63] = feat[base*DP + i];
    __syncthreads();

    float acc[P];
    {
        float bb = fc1b[t];
        #pragma unroll
        for (int p = 0; p < P; ++p) acc[p] = bb;
        for (int c = 0; c < DP; ++c) {
            float w = fc1w[c*DM + t];
            #pragma unroll
            for (int p = 0; p < P; ++p) acc[p] = fmaf(fsh[p][c], w, acc[p]);
        }
    }
    #pragma unroll
    for (int p = 0; p < P; ++p) xsh[p][t] = acc[p];
    __syncthreads();

    const float* Ws[3] = { wq, wk, wv };
    float* Os[3] = { g_q, g_kf, g_vf };
    for (int m = 0; m < 3; ++m) {
        const float* W = Ws[m];
        #pragma unroll
        for (int p = 0; p < P; ++p) acc[p] = 0.f;
        for (int c = 0; c < DM; c += 4) {
            float w0 = W[(c+0)*DM + t];
            float w1 = W[(c+1)*DM + t];
            float w2 = W[(c+2)*DM + t];
            float w3 = W[(c+3)*DM + t];
            #pragma unroll
            for (int p = 0; p < P; ++p) {
                float4 x4 = *reinterpret_cast<const float4*>(&xsh[p][c]);
                acc[p] = fmaf(x4.x, w0, fmaf(x4.y, w1, fmaf(x4.z, w2, fmaf(x4.w, w3, acc[p]))));
            }
        }
        float* O = Os[m];
        #pragma unroll
        for (int p = 0; p < P; ++p) O[(base + p)*DM + t] = acc[p];
    }
}

// KNN: one query per thread; whole batch cloud staged in smem.
// Per-lane sorted top-16 with (dist, index) lexicographic order
// (identical formula + tie-break to jax.lax.top_k selection).
__device__ __forceinline__ void knn_body(
    float* xyzsh, int blk, const float* __restrict__ xyz)
{
    int t = threadIdx.x;
    int q = blk * 128 + t;                // global query id; whole block same batch
    int b = q >> 12;

    const float4* src = reinterpret_cast<const float4*>(xyz + (size_t)b * NPTS * 3);
    float4* dst = reinterpret_cast<float4*>(xyzsh);
    #pragma unroll
    for (int i = 0; i < (NPTS*3/4)/128; ++i)   // 24 float4 per thread
        dst[t + 128*i] = src[t + 128*i];
    __syncthreads();

    int n = q & (NPTS - 1);
    float qx = xyzsh[n*3+0], qy = xyzsh[n*3+1], qz = xyzsh[n*3+2];
    float qsq = fmaf(qz, qz, fmaf(qy, qy, qx*qx));

    float bd[KNBR]; int bi[KNBR];
    #pragma unroll
    for (int i = 0; i < KNBR; ++i) { bd[i] = INFINITY; bi[i] = 0x7fffffff; }

    for (int m = 0; m < NPTS; ++m) {
        float cx = xyzsh[m*3+0], cy = xyzsh[m*3+1], cz = xyzsh[m*3+2];
        float csq = fmaf(cz, cz, fmaf(cy, cy, cx*cx));
        float dot = fmaf(qz, cz, fmaf(qy, cy, qx*cx));
        float d = (qsq + csq) - 2.0f * dot;   // same formula as reference

        if ((d < bd[KNBR-1]) || (d == bd[KNBR-1] && m < bi[KNBR-1])) {
            bd[KNBR-1] = d; bi[KNBR-1] = m;
            #pragma unroll
            for (int j = KNBR-1; j > 0; --j) {
                bool sw = (bd[j] < bd[j-1]) || (bd[j] == bd[j-1] && bi[j] < bi[j-1]);
                if (sw) {
                    float td = bd[j]; bd[j] = bd[j-1]; bd[j-1] = td;
                    int   ti = bi[j]; bi[j] = bi[j-1]; bi[j-1] = ti;
                }
            }
        }
    }

    int4* O = reinterpret_cast<int4*>(&g_knn[q*KNBR]);
    O[0] = make_int4(bi[0],  bi[1],  bi[2],  bi[3]);
    O[1] = make_int4(bi[4],  bi[5],  bi[6],  bi[7]);
    O[2] = make_int4(bi[8],  bi[9],  bi[10], bi[11]);
    O[3] = make_int4(bi[12], bi[13], bi[14], bi[15]);
}

__global__ __launch_bounds__(128) void ab_kernel(
    const float* __restrict__ xyz, const float* __restrict__ feat,
    const float* __restrict__ fc1w, const float* __restrict__ fc1b,
    const float* __restrict__ wq, const float* __restrict__ wk,
    const float* __restrict__ wv)
{
    __shared__ ABSmem sm;
    if (blockIdx.x < KNNB)
        knn_body(sm.xyzsh, blockIdx.x, xyz);
    else
        qkv_body(sm.q, blockIdx.x - KNNB, feat, fc1w, fc1b, wq, wk, wv);
}

// ============================================================
// Kernel C: fused MLP chain. Thread t owns 2 channels
//   {ch0, ch0+64} (ch0 = t&63) and 16 slots of one point
//   (hs = t>>6). Per c-iter: 4 LDS.128 + 2 LDG + 16 FFMA2
//   -> FMA-pipe-bound (was LDS-bound at 8 LDS.128 : 16 FFMA2).
// ============================================================
__global__ __launch_bounds__(128, 3) void point_kernel(
    const float* __restrict__ xyz, const float* __restrict__ feat,
    const float* __restrict__ fd1w, const float* __restrict__ fd1b,
    const float* __restrict__ fd2w, const float* __restrict__ fd2b,
    const float* __restrict__ fg1w, const float* __restrict__ fg1b,
    const float* __restrict__ fg2w, const float* __restrict__ fg2b,
    const float* __restrict__ fc2w, const float* __restrict__ fc2b,
    float* __restrict__ out_res, float* __restrict__ out_diff)
{
    __shared__ float bufH[DM][KROW];   // h1 -> h2 -> cv
    __shared__ float bufT[DM][KROW];   // tt -> diff
    __shared__ float psh[NS][DP];      // cv-half partials of fc2
    __shared__ float relsh[NS][4];
    __shared__ int   idxsh[NS];

    int t = threadIdx.x;
    int pid0 = blockIdx.x * PPB;
    int b = pid0 >> 12;

    int ch0 = t & 63;                  // owns channels ch0, ch0+64
    int hs  = t >> 6;                  // slot half == point index
    int sb  = hs * 16;                 // slot base
    int pid = pid0 + hs;               // point owning this thread's slots

    if (t < NS) {
        int p = t >> 4, k = t & 15;
        int qp = pid0 + p;
        int idx = g_knn[qp*KNBR + k];
        idxsh[t] = idx;
        int gpt = (b << 12) + idx;
        relsh[t][0] = xyz[qp*3+0] - xyz[gpt*3+0];
        relsh[t][1] = xyz[qp*3+1] - xyz[gpt*3+1];
        relsh[t][2] = xyz[qp*3+2] - xyz[gpt*3+2];
    }
    __syncthreads();

    // ---- stage 1: h1 = relu(rel @ fd1 + b) -> bufH rows ch0, ch0+64
    {
        float w0a = fd1w[ch0],    w1a = fd1w[DM+ch0],    w2a = fd1w[2*DM+ch0],    ba = fd1b[ch0];
        float w0b = fd1w[ch0+64], w1b = fd1w[DM+ch0+64], w2b = fd1w[2*DM+ch0+64], bc = fd1b[ch0+64];
        #pragma unroll
        for (int j = 0; j < 4; ++j) {
            int s0 = sb + 4*j;
            float4 va, vb;
            {
                float r0=relsh[s0+0][0], r1=relsh[s0+0][1], r2=relsh[s0+0][2];
                va.x = fmaxf(fmaf(r0,w0a,fmaf(r1,w1a,fmaf(r2,w2a,ba))), 0.f);
                vb.x = fmaxf(fmaf(r0,w0b,fmaf(r1,w1b,fmaf(r2,w2b,bc))), 0.f);
            }
            {
                float r0=relsh[s0+1][0], r1=relsh[s0+1][1], r2=relsh[s0+1][2];
                va.y = fmaxf(fmaf(r0,w0a,fmaf(r1,w1a,fmaf(r2,w2a,ba))), 0.f);
                vb.y = fmaxf(fmaf(r0,w0b,fmaf(r1,w1b,fmaf(r2,w2b,bc))), 0.f);
            }
            {
                float r0=relsh[s0+2][0], r1=relsh[s0+2][1], r2=relsh[s0+2][2];
                va.z = fmaxf(fmaf(r0,w0a,fmaf(r1,w1a,fmaf(r2,w2a,ba))), 0.f);
                vb.z = fmaxf(fmaf(r0,w0b,fmaf(r1,w1b,fmaf(r2,w2b,bc))), 0.f);
            }
            {
                float r0=relsh[s0+3][0], r1=relsh[s0+3][1], r2=relsh[s0+3][2];
                va.w = fmaxf(fmaf(r0,w0a,fmaf(r1,w1a,fmaf(r2,w2a,ba))), 0.f);
                vb.w = fmaxf(fmaf(r0,w0b,fmaf(r1,w1b,fmaf(r2,w2b,bc))), 0.f);
            }
            *reinterpret_cast<float4*>(&bufH[ch0][s0])    = va;
            *reinterpret_cast<float4*>(&bufH[ch0+64][s0]) = vb;
        }
    }
    __syncthreads();

    ull peA[8], peB[8];   // pos_enc: 2 channels x 16 slots; lives to stage 6

    // ---- stage 2: pe = h1 @ fd2 + b
    {
        float ba = fd2b[ch0], bc = fd2b[ch0+64];
        ull bA = pack2(ba, ba), bB = pack2(bc, bc);
        #pragma unroll
        for (int j = 0; j < 8; ++j) { peA[j] = bA; peB[j] = bB; }
        #pragma unroll 2
        for (int c = 0; c < DM; ++c) {
            float wa = fd2w[c*DM + ch0], wb = fd2w[c*DM + ch0 + 64];
            ull wa2 = pack2(wa, wa), wb2 = pack2(wb, wb);
            const ulonglong2* row = reinterpret_cast<const ulonglong2*>(&bufH[c][sb]);
            #pragma unroll
            for (int j = 0; j < 4; ++j) {
                ulonglong2 h = row[j];
                peA[2*j+0] = ffma2(h.x, wa2, peA[2*j+0]);
                peA[2*j+1] = ffma2(h.y, wa2, peA[2*j+1]);
                peB[2*j+0] = ffma2(h.x, wb2, peB[2*j+0]);
                peB[2*j+1] = ffma2(h.y, wb2, peB[2*j+1]);
            }
        }
    }

    // ---- stage 3: tt = q - kf + pe -> bufT rows ch0, ch0+64
    {
        float qa = g_q[pid*DM + ch0];
        float qb = g_q[pid*DM + ch0 + 64];
        float kfa[16], kfb[16];
        #pragma unroll
        for (int i = 0; i < 16; ++i) {
            int gpt = (b << 12) + idxsh[sb + i];
            kfa[i] = g_kf[gpt*DM + ch0];
            kfb[i] = g_kf[gpt*DM + ch0 + 64];
        }
        #pragma unroll
        for (int j = 0; j < 4; ++j) {
            float p0,p1,p2,p3;
            unpack2(peA[2*j+0], p0, p1); unpack2(peA[2*j+1], p2, p3);
            float4 va;
            va.x = qa - kfa[4*j+0] + p0;
            va.y = qa - kfa[4*j+1] + p1;
            va.z = qa - kfa[4*j+2] + p2;
            va.w = qa - kfa[4*j+3] + p3;
            *reinterpret_cast<float4*>(&bufT[ch0][sb+4*j]) = va;
            unpack2(peB[2*j+0], p0, p1); unpack2(peB[2*j+1], p2, p3);
            float4 vb;
            vb.x = qb - kfb[4*j+0] + p0;
            vb.y = qb - kfb[4*j+1] + p1;
            vb.z = qb - kfb[4*j+2] + p2;
            vb.w = qb - kfb[4*j+3] + p3;
            *reinterpret_cast<float4*>(&bufT[ch0+64][sb+4*j]) = vb;
        }
    }
    __syncthreads();   // stage-2 bufH reads done; tt visible

    // ---- stage 4: h2 = relu(tt @ fg1 + b) -> bufH
    {
        ull aA[8], aB[8];
        float ba = fg1b[ch0], bc = fg1b[ch0+64];
        ull bA = pack2(ba, ba), bB = pack2(bc, bc);
        #pragma unroll
        for (int j = 0; j < 8; ++j) { aA[j] = bA; aB[j] = bB; }
        #pragma unroll 2
        for (int c = 0; c < DM; ++c) {
            float wa = fg1w[c*DM + ch0], wb = fg1w[c*DM + ch0 + 64];
            ull wa2 = pack2(wa, wa), wb2 = pack2(wb, wb);
            const ulonglong2* row = reinterpret_cast<const ulonglong2*>(&bufT[c][sb]);
            #pragma unroll
            for (int j = 0; j < 4; ++j) {
                ulonglong2 h = row[j];
                aA[2*j+0] = ffma2(h.x, wa2, aA[2*j+0]);
                aA[2*j+1] = ffma2(h.y, wa2, aA[2*j+1]);
                aB[2*j+0] = ffma2(h.x, wb2, aB[2*j+0]);
                aB[2*j+1] = ffma2(h.y, wb2, aB[2*j+1]);
            }
        }
        #pragma unroll
        for (int j = 0; j < 4; ++j) {
            float p0,p1,p2,p3;
            unpack2(aA[2*j+0], p0, p1); unpack2(aA[2*j+1], p2, p3);
            float4 va; va.x=fmaxf(p0,0.f); va.y=fmaxf(p1,0.f); va.z=fmaxf(p2,0.f); va.w=fmaxf(p3,0.f);
            *reinterpret_cast<float4*>(&bufH[ch0][sb+4*j]) = va;
            unpack2(aB[2*j+0], p0, p1); unpack2(aB[2*j+1], p2, p3);
            float4 vb; vb.x=fmaxf(p0,0.f); vb.y=fmaxf(p1,0.f); vb.z=fmaxf(p2,0.f); vb.w=fmaxf(p3,0.f);
            *reinterpret_cast<float4*>(&bufH[ch0+64][sb+4*j]) = vb;
        }
    }
    __syncthreads();   // h2 visible; stage-4 bufT reads done

    // ---- stage 5: diff = h2 @ fg2 + b -> out_diff + bufT
    {
        ull aA[8], aB[8];
        float ba = fg2b[ch0], bc = fg2b[ch0+64];
        ull bA = pack2(ba, ba), bB = pack2(bc, bc);
        #pragma unroll
        for (int j = 0; j < 8; ++j) { aA[j] = bA; aB[j] = bB; }
        #pragma unroll 2
        for (int c = 0; c < DM; ++c) {
            float wa = fg2w[c*DM + ch0], wb = fg2w[c*DM + ch0 + 64];
            ull wa2 = pack2(wa, wa), wb2 = pack2(wb, wb);
            const ulonglong2* row = reinterpret_cast<const ulonglong2*>(&bufH[c][sb]);
            #pragma unroll
            for (int j = 0; j < 4; ++j) {
                ulonglong2 h = row[j];
                aA[2*j+0] = ffma2(h.x, wa2, aA[2*j+0]);
                aA[2*j+1] = ffma2(h.y, wa2, aA[2*j+1]);
                aB[2*j+0] = ffma2(h.x, wb2, aB[2*j+0]);
                aB[2*j+1] = ffma2(h.y, wb2, aB[2*j+1]);
            }
        }
        float* ODa = out_diff + (size_t)pid*KNBR*DM + ch0;      // slot i -> ODa[i*DM]
        float* ODb = ODa + 64;
        #pragma unroll
        for (int j = 0; j < 4; ++j) {
            float p0,p1,p2,p3;
            unpack2(aA[2*j+0], p0, p1); unpack2(aA[2*j+1], p2, p3);
            ODa[(4*j+0)*DM]=p0; ODa[(4*j+1)*DM]=p1; ODa[(4*j+2)*DM]=p2; ODa[(4*j+3)*DM]=p3;
            float4 va; va.x=p0; va.y=p1; va.z=p2; va.w=p3;
            *reinterpret_cast<float4*>(&bufT[ch0][sb+4*j]) = va;
            unpack2(aB[2*j+0], p0, p1); unpack2(aB[2*j+1], p2, p3);
            ODb[(4*j+0)*DM]=p0; ODb[(4*j+1)*DM]=p1; ODb[(4*j+2)*DM]=p2; ODb[(4*j+3)*DM]=p3;
            float4 vb; vb.x=p0; vb.y=p1; vb.z=p2; vb.w=p3;
            *reinterpret_cast<float4*>(&bufT[ch0+64][sb+4*j]) = vb;
        }
    }
    __syncthreads();   // stage-5 bufH reads done; diff visible

    // ---- stage 6: cv = vf + pe -> bufH
    {
        float vfa[16], vfb[16];
        #pragma unroll
        for (int i = 0; i < 16; ++i) {
            int gpt = (b << 12) + idxsh[sb + i];
            vfa[i] = g_vf[gpt*DM + ch0];
            vfb[i] = g_vf[gpt*DM + ch0 + 64];
        }
        #pragma unroll
        for (int j = 0; j < 4; ++j) {
            float p0,p1,p2,p3;
            unpack2(peA[2*j+0], p0, p1); unpack2(peA[2*j+1], p2, p3);
            float4 va;
            va.x = vfa[4*j+0] + p0; va.y = vfa[4*j+1] + p1;
            va.z = vfa[4*j+2] + p2; va.w = vfa[4*j+3] + p3;
            *reinterpret_cast<float4*>(&bufH[ch0][sb+4*j]) = va;
            unpack2(peB[2*j+0], p0, p1); unpack2(peB[2*j+1], p2, p3);
            float4 vb;
            vb.x = vfb[4*j+0] + p0; vb.y = vfb[4*j+1] + p1;
            vb.z = vfb[4*j+2] + p2; vb.w = vfb[4*j+3] + p3;
            *reinterpret_cast<float4*>(&bufH[ch0+64][sb+4*j]) = vb;
        }
    }
    __syncthreads();

    // ---- stage 7: out = [diff, cv] @ fc2 + b ; res = max_k + feat
    //   thread: dp = t&31 -> d-channels {dp, dp+32}; hsrc = (t>>5)&1 -> src buf;
    //   sg = t>>6 -> slots [16sg, 16sg+16) (= point sg)
    {
        int dp = t & 31;
        int hsrc = (t >> 5) & 1;
        int sg = t >> 6;
        int sb7 = sg * 16;
        const float (*src)[KROW] = hsrc ? bufH : bufT;   // 1: cv, 0: diff
        const float* W = fc2w + hsrc*DM*DP;
        ull aA[8], aB[8];
        #pragma unroll
        for (int j = 0; j < 8; ++j) { aA[j] = 0; aB[j] = 0; }
        #pragma unroll 2
        for (int c = 0; c < DM; ++c) {
            float wa = W[c*DP + dp], wb = W[c*DP + dp + 32];
            ull wa2 = pack2(wa, wa), wb2 = pack2(wb, wb);
            const ulonglong2* row = reinterpret_cast<const ulonglong2*>(&src[c][sb7]);
            #pragma unroll
            for (int j = 0; j < 4; ++j) {
                ulonglong2 h = row[j];
                aA[2*j+0] = ffma2(h.x, wa2, aA[2*j+0]);
                aA[2*j+1] = ffma2(h.y, wa2, aA[2*j+1]);
                aB[2*j+0] = ffma2(h.x, wb2, aB[2*j+0]);
                aB[2*j+1] = ffma2(h.y, wb2, aB[2*j+1]);
            }
        }
        float pa[16], pb[16];
        #pragma unroll
        for (int j = 0; j < 8; ++j) { unpack2(aA[j], pa[2*j], pa[2*j+1]); unpack2(aB[j], pb[2*j], pb[2*j+1]); }
        if (hsrc) {
            #pragma unroll
            for (int i = 0; i < 16; ++i) {
                psh[sb7+i][dp]    = pa[i];
                psh[sb7+i][dp+32] = pb[i];
            }
        }
        __syncthreads();
        if (!hsrc) {
            float bba = fc2b[dp], bbb = fc2b[dp+32];
            float ma = -INFINITY, mb = -INFINITY;
            #pragma unroll
            for (int i = 0; i < 16; ++i) {
                ma = fmaxf(ma, pa[i] + psh[sb7+i][dp]    + bba);
                mb = fmaxf(mb, pb[i] + psh[sb7+i][dp+32] + bbb);
            }
            out_res[(pid0+sg)*DP + dp]      = ma + feat[(pid0+sg)*DP + dp];
            out_res[(pid0+sg)*DP + dp + 32] = mb + feat[(pid0+sg)*DP + dp + 32];
        }
    }
}

// ============================================================
extern "C" void kernel_launch(void* const* d_in, const int* in_sizes, int n_in,
                              void* d_out, int out_size)
{
    const float* xyz  = (const float*)d_in[0];
    const float* feat = (const float*)d_in[1];
    const float* fc1w = (const float*)d_in[2];
    const float* fc1b = (const float*)d_in[3];
    const float* fc2w = (const float*)d_in[4];
    const float* fc2b = (const float*)d_in[5];
    const float* fd1w = (const float*)d_in[6];
    const float* fd1b = (const float*)d_in[7];
    const float* fd2w = (const float*)d_in[8];
    const float* fd2b = (const float*)d_in[9];
    const float* fg1w = (const float*)d_in[10];
    const float* fg1b = (const float*)d_in[11];
    const float* fg2w = (const float*)d_in[12];
    const float* fg2b = (const float*)d_in[13];
    const float* wq   = (const float*)d_in[14];
    const float* wk   = (const float*)d_in[15];
    const float* wv   = (const float*)d_in[16];

    float* out_res  = (float*)d_out;                       // (B,N,DP)
    float* out_diff = out_res + (size_t)BATCH*NPTS*DP;     // (B,N,K,DM)

    ab_kernel   <<<KNNB + QKVB,    128>>>(xyz, feat, fc1w, fc1b, wq, wk, wv);
    point_kernel<<<BATCH*NPTS/PPB, 128>>>(xyz, feat,
                                          fd1w, fd1b, fd2w, fd2b,
                                          fg1w, fg1b, fg2w, fg2b,
                                          fc2w, fc2b, out_res, out_diff);
}